// round 15
// baseline (speedup 1.0000x reference)
#include <cuda_runtime.h>
#include <cuda_fp16.h>
#include <cstdint>

// Problem constants
#define B_   4
#define C_   256
#define N_   4096          // H*W = 64*64
#define NH_  4
#define HD_  64
#define NG_  8
#define CPG_ 32
#define EPS_ 1e-5f
#define SCALE_ 0.125f      // HD^-0.5
#define LOG2E_ 1.4426950408889634f

// Scratch
__device__ uint16_t g_hnt [(size_t)B_ * N_ * C_];       // GN output, fp16 [b][n][c]
__device__ uint16_t g_qkvh[(size_t)B_ * 3 * C_ * N_];   // QKV fp16 [b][3C][n]
__device__ uint16_t g_aot [(size_t)B_ * N_ * C_];       // attn out fp16 [b][n][c]
__device__ uint16_t g_w16 [(3 * C_ + C_) * C_];         // qkv_w + proj_w fp16
__device__ float    g_part[256 * 2];                    // partial GN sums

// ---------------------------------------------------------------------------
// helpers
// ---------------------------------------------------------------------------
__device__ __forceinline__ float ex2f(float x) {
    float y;
    asm("ex2.approx.ftz.f32 %0, %1;" : "=f"(y) : "f"(x));
    return y;
}
__device__ __forceinline__ uint32_t f16x2(float a, float b) {   // {lo:a, hi:b}
    uint32_t r;
    asm("cvt.rn.f16x2.f32 %0, %1, %2;" : "=r"(r) : "f"(b), "f"(a));
    return r;
}
__device__ __forceinline__ uint32_t smem_u32(const void* p) {
    uint32_t a;
    asm("{ .reg .u64 t; cvta.to.shared.u64 t, %1; cvt.u32.u64 %0, t; }" : "=r"(a) : "l"(p));
    return a;
}
__device__ __forceinline__ void cpa16(uint32_t s, const void* g) {
    asm volatile("cp.async.cg.shared.global [%0], [%1], 16;" :: "r"(s), "l"(g));
}
__device__ __forceinline__ void cpa_commit() { asm volatile("cp.async.commit_group;"); }
__device__ __forceinline__ void cpa_wait1()  { asm volatile("cp.async.wait_group 1;"); }
__device__ __forceinline__ void cpa_wait0()  { asm volatile("cp.async.wait_group 0;"); }

__device__ __forceinline__ void ldsm4(uint32_t& r0, uint32_t& r1, uint32_t& r2, uint32_t& r3,
                                      uint32_t a) {
    asm volatile("ldmatrix.sync.aligned.m8n8.x4.shared.b16 {%0,%1,%2,%3}, [%4];"
                 : "=r"(r0), "=r"(r1), "=r"(r2), "=r"(r3) : "r"(a));
}
__device__ __forceinline__ void ldsm4t(uint32_t& r0, uint32_t& r1, uint32_t& r2, uint32_t& r3,
                                       uint32_t a) {
    asm volatile("ldmatrix.sync.aligned.m8n8.x4.trans.shared.b16 {%0,%1,%2,%3}, [%4];"
                 : "=r"(r0), "=r"(r1), "=r"(r2), "=r"(r3) : "r"(a));
}
__device__ __forceinline__ void mma_f16(float* d, const uint32_t* a, const uint32_t* b) {
    asm("mma.sync.aligned.m16n8k16.row.col.f32.f16.f16.f32 "
        "{%0,%1,%2,%3}, {%4,%5,%6,%7}, {%8,%9}, {%0,%1,%2,%3};"
        : "+f"(d[0]), "+f"(d[1]), "+f"(d[2]), "+f"(d[3])
        : "r"(a[0]), "r"(a[1]), "r"(a[2]), "r"(a[3]), "r"(b[0]), "r"(b[1]));
}

// ---------------------------------------------------------------------------
// GroupNorm statistics, phase 1: 256 blocks, 8 partials per (b,g)
// ---------------------------------------------------------------------------
__global__ void gn_stats1_k(const float* __restrict__ x) {
    int blk = blockIdx.x;
    int bg = blk >> 3, part = blk & 7;
    const float4* base = (const float4*)(x + (size_t)bg * CPG_ * N_) + part * 4096;
    int tid = threadIdx.x;
    float s = 0.f, s2 = 0.f;
    for (int i = tid; i < 4096; i += 256) {
        float4 v = base[i];
        s  += v.x + v.y + v.z + v.w;
        s2 += v.x * v.x + v.y * v.y + v.z * v.z + v.w * v.w;
    }
    __shared__ float rs[256], rq[256];
    rs[tid] = s; rq[tid] = s2;
    __syncthreads();
    for (int o = 128; o > 0; o >>= 1) {
        if (tid < o) { rs[tid] += rs[tid + o]; rq[tid] += rq[tid + o]; }
        __syncthreads();
    }
    if (tid == 0) {
        g_part[blk * 2 + 0] = rs[0];
        g_part[blk * 2 + 1] = rq[0];
    }
}

// ---------------------------------------------------------------------------
// GroupNorm apply + transpose, with inline phase-2 stats reduction.
// x[b][c][n] fp32 -> g_hnt[b][n][c] fp16. Grid (N/64, C/64, B), 256 thr.
// ---------------------------------------------------------------------------
__global__ void gn_t_k(const float* __restrict__ x,
                       const float* __restrict__ gw,
                       const float* __restrict__ gb) {
    int n0 = blockIdx.x * 64, c0 = blockIdx.y * 64, b = blockIdx.z;
    int t = threadIdx.x;

    __shared__ __half ht[64][72];
    __shared__ float sstat[2][2];    // two groups per 64-channel block

    if (t < 2) {
        int g_abs = b * NG_ + (c0 >> 5) + t;
        float s = 0.f, s2 = 0.f;
#pragma unroll
        for (int p = 0; p < 8; p++) {
            s  += g_part[(g_abs * 8 + p) * 2 + 0];
            s2 += g_part[(g_abs * 8 + p) * 2 + 1];
        }
        const float invn = 1.f / (float)(CPG_ * N_);
        float mean = s * invn;
        float var  = s2 * invn - mean * mean;
        sstat[t][0] = mean;
        sstat[t][1] = rsqrtf(var + EPS_);
    }
    __syncthreads();

    int n_l = t & 63, cq = t >> 6;
#pragma unroll
    for (int it = 0; it < 16; it++) {
        int c_l = it * 4 + cq;
        int c = c0 + c_l;
        int gi = c_l >> 5;
        float mean = sstat[gi][0];
        float rstd = sstat[gi][1];
        float ga = gw[c] * rstd;
        float be = gb[c] - mean * ga;
        float v = x[((size_t)b * C_ + c) * N_ + n0 + n_l];
        ht[c_l][n_l] = __float2half(v * ga + be);
    }
    __syncthreads();

    int n_o = t >> 2, ch = t & 3;
    uint32_t pk[8];
#pragma unroll
    for (int u = 0; u < 8; u++) {
        __half2 h2 = __halves2half2(ht[ch * 16 + 2 * u][n_o], ht[ch * 16 + 2 * u + 1][n_o]);
        pk[u] = *(uint32_t*)&h2;
    }
    uint16_t* orow = g_hnt + ((size_t)b * N_ + n0 + n_o) * C_ + c0 + ch * 16;
    *(uint4*)(orow)     = *(uint4*)&pk[0];
    *(uint4*)(orow + 8) = *(uint4*)&pk[4];
}

// ---------------------------------------------------------------------------
// Weight pack fp32 -> fp16 (both weights in one launch)
// ---------------------------------------------------------------------------
#define QKVW4 (3 * C_ * C_ / 4)   // 49152 float4
#define ALLW4 (QKVW4 + C_ * C_ / 4)
__global__ void w2h_k(const float* __restrict__ qkvw, const float* __restrict__ pw) {
    int i = blockIdx.x * 256 + threadIdx.x;
    if (i >= ALLW4) return;
    float4 v = (i < QKVW4) ? ((const float4*)qkvw)[i] : ((const float4*)pw)[i - QKVW4];
    uint2 o;
    o.x = f16x2(v.x, v.y);
    o.y = f16x2(v.z, v.w);
    *(uint2*)(g_w16 + (size_t)i * 4) = o;
}

// ---------------------------------------------------------------------------
// fp16 tensor-core GEMM (ldmatrix B-frags): Out = W16 @ Bt^T + bias
// Single-sync pipeline: wait -> sync -> prefetch(next) -> compute.
// ---------------------------------------------------------------------------
__global__ __launch_bounds__(128) void hgemm_k(const uint16_t* __restrict__ W16,
                                               const uint16_t* __restrict__ Bt,
                                               const float* __restrict__ bias,
                                               const float* __restrict__ res,
                                               uint16_t* __restrict__ outh,
                                               float* __restrict__ outf,
                                               int M) {
    const int K = C_;
    int b  = blockIdx.z;
    const uint16_t* Btb = Bt + (size_t)b * N_ * K;
    int m0 = blockIdx.y * 64, n0 = blockIdx.x * 64;

    __shared__ uint16_t Bs[2][64 * 72];
    uint32_t bsm[2] = { smem_u32(Bs[0]), smem_u32(Bs[1]) };

    int tid = threadIdx.x, w = tid >> 5, lane = tid & 31;
    int g = lane >> 2, m = lane & 3;
    int r_lo = m0 + w * 16 + g, r_hi = r_lo + 8;
    uint32_t lmrow = (uint32_t)((lane & 7) * 144 + (lane >> 3) * 16);

    float acc[8][4];
#pragma unroll
    for (int j = 0; j < 8; j++)
#pragma unroll
        for (int i = 0; i < 4; i++) acc[j][i] = 0.f;

    const int NS = K / 32;
    {
#pragma unroll
        for (int it = 0; it < 2; it++) {
            int idx = it * 128 + tid;
            int r = idx >> 2, c = idx & 3;
            cpa16(bsm[0] + (uint32_t)(r * 144 + c * 16),
                  Btb + (size_t)(n0 + r) * K + c * 8);
        }
        cpa_commit();
    }
    for (int ks = 0; ks < NS; ks++) {
        cpa_wait0();
        __syncthreads();
        if (ks + 1 < NS) {
            int s = (ks + 1) & 1, k0 = (ks + 1) * 32;
#pragma unroll
            for (int it = 0; it < 2; it++) {
                int idx = it * 128 + tid;
                int r = idx >> 2, c = idx & 3;
                cpa16(bsm[s] + (uint32_t)(r * 144 + c * 16),
                      Btb + (size_t)(n0 + r) * K + k0 + c * 8);
            }
            cpa_commit();
        }
        int k0 = ks * 32;
        uint32_t a0[4], a1[4];
        {
            int kk = k0 + 2 * m;
            a0[0] = *(const uint32_t*)&W16[(size_t)r_lo * K + kk];
            a0[1] = *(const uint32_t*)&W16[(size_t)r_hi * K + kk];
            a0[2] = *(const uint32_t*)&W16[(size_t)r_lo * K + kk + 8];
            a0[3] = *(const uint32_t*)&W16[(size_t)r_hi * K + kk + 8];
            a1[0] = *(const uint32_t*)&W16[(size_t)r_lo * K + kk + 16];
            a1[1] = *(const uint32_t*)&W16[(size_t)r_hi * K + kk + 16];
            a1[2] = *(const uint32_t*)&W16[(size_t)r_lo * K + kk + 24];
            a1[3] = *(const uint32_t*)&W16[(size_t)r_hi * K + kk + 24];
        }
        uint32_t bbase = bsm[ks & 1] + lmrow;
#pragma unroll
        for (int j = 0; j < 8; j++) {
            uint32_t b0, b1, b2, b3;
            ldsm4(b0, b1, b2, b3, bbase + (uint32_t)(j * 1152));
            uint32_t bf0[2] = { b0, b1 };
            uint32_t bf1[2] = { b2, b3 };
            mma_f16(acc[j], a0, bf0);
            mma_f16(acc[j], a1, bf1);
        }
    }

    float b_lo = bias[r_lo], b_hi = bias[r_hi];
    if (outh) {
        uint16_t* Ob = outh + (size_t)b * M * N_;
#pragma unroll
        for (int j = 0; j < 8; j++) {
            int n = n0 + j * 8 + 2 * m;
            *(uint32_t*)&Ob[(size_t)r_lo * N_ + n] = f16x2(acc[j][0] + b_lo, acc[j][1] + b_lo);
            *(uint32_t*)&Ob[(size_t)r_hi * N_ + n] = f16x2(acc[j][2] + b_hi, acc[j][3] + b_hi);
        }
    } else {
        float* Ob = outf + (size_t)b * M * N_;
        const float* resb = res + (size_t)b * M * N_;
#pragma unroll
        for (int j = 0; j < 8; j++) {
            int n = n0 + j * 8 + 2 * m;
            size_t olo = (size_t)r_lo * N_ + n;
            size_t ohi = (size_t)r_hi * N_ + n;
            float2 rl = *(const float2*)&resb[olo];
            float2 rh = *(const float2*)&resb[ohi];
            float2 vlo; vlo.x = acc[j][0] + b_lo + rl.x; vlo.y = acc[j][1] + b_lo + rl.y;
            float2 vhi; vhi.x = acc[j][2] + b_hi + rh.x; vhi.y = acc[j][3] + b_hi + rh.y;
            *(float2*)&Ob[olo] = vlo;
            *(float2*)&Ob[ohi] = vhi;
        }
    }
}

// ---------------------------------------------------------------------------
// Flash attention (R9 geometry: 64q/CTA, 4 warps). K loaded via trans-ldmatrix
// directly from d-major qkvh (no repack). Single-sync 3-stage cp.async.
// K smem [d][key] (like V), stride 72 halfwords.
// ---------------------------------------------------------------------------
#define ATT_STG   18432          // bytes per stage (K 9216 + V 9216)
#define ATT_SMEM  (3 * ATT_STG)  // 55296

__device__ __forceinline__ void attn_prefetch(uint32_t base, int stg,
                                              const uint16_t* khb, const uint16_t* vhb,
                                              int k0t, int tid) {
    uint32_t kb = base + (uint32_t)stg * ATT_STG;
    uint32_t vb = kb + 9216;
#pragma unroll
    for (int it = 0; it < 4; it++) {
        int idx = it * 128 + tid;
        int r = idx >> 3, c = idx & 7;
        cpa16(kb + (uint32_t)(r * 144 + c * 16), khb + (size_t)r * N_ + k0t + c * 8);
    }
#pragma unroll
    for (int it = 0; it < 4; it++) {
        int idx = it * 128 + tid;
        int r = idx >> 3, c = idx & 7;
        cpa16(vb + (uint32_t)(r * 144 + c * 16), vhb + (size_t)r * N_ + k0t + c * 8);
    }
    cpa_commit();
}

__global__ __launch_bounds__(128, 4) void attn_k() {
    int qt = blockIdx.x, h = blockIdx.y, b = blockIdx.z;
    const uint16_t* qb  = g_qkvh + ((size_t)b * 3 * C_ + h * HD_) * N_;
    const uint16_t* khb = g_qkvh + ((size_t)b * 3 * C_ + C_ + h * HD_) * N_;
    const uint16_t* vhb = g_qkvh + ((size_t)b * 3 * C_ + 2 * C_ + h * HD_) * N_;

    extern __shared__ uint16_t smh[];
    uint32_t base = smem_u32(smh);

    int tid = threadIdx.x, w = tid >> 5, lane = tid & 31;
    int g = lane >> 2, m = lane & 3;
    int q0 = qt * 64;
    uint32_t lmrow  = (uint32_t)((lane & 7) * 144 + (lane >> 3) * 16);  // V (non-trans)
    uint32_t lmrowt = (uint32_t)(lane * 144);                           // K (trans: 32 d-rows)

    attn_prefetch(base, 0, khb, vhb, 0, tid);
    attn_prefetch(base, 1, khb, vhb, 64, tid);

    // Q A-fragments (fp16), scaled for log2-domain softmax
    const float qs = SCALE_ * LOG2E_;
    uint32_t Aq[4][4];
    int qlo = q0 + w * 16 + g, qhi = qlo + 8;
#pragma unroll
    for (int t = 0; t < 4; t++) {
        int d0 = t * 16 + 2 * m;
#pragma unroll
        for (int hseg = 0; hseg < 2; hseg++) {
            int d = d0 + hseg * 8;
            float a0 = __half2float(__ushort_as_half(qb[(size_t)d * N_ + qlo])) * qs;
            float a1 = __half2float(__ushort_as_half(qb[(size_t)(d + 1) * N_ + qlo])) * qs;
            float a2 = __half2float(__ushort_as_half(qb[(size_t)d * N_ + qhi])) * qs;
            float a3 = __half2float(__ushort_as_half(qb[(size_t)(d + 1) * N_ + qhi])) * qs;
            Aq[t][2 * hseg]     = f16x2(a0, a1);
            Aq[t][2 * hseg + 1] = f16x2(a2, a3);
        }
    }

    float O[8][4];
#pragma unroll
    for (int j = 0; j < 8; j++)
#pragma unroll
        for (int i = 0; i < 4; i++) O[j][i] = 0.f;
    float mlo = -1e30f, mhi = -1e30f, slo = 0.f, shi = 0.f;

    const int NT = N_ / 64;
    for (int kt = 0; kt < NT; kt++) {
        if (kt + 1 < NT) {
            cpa_wait1();
        } else {
            cpa_wait0();
        }
        __syncthreads();               // orders prev-iter reads before refill below
        if (kt + 2 < NT) {
            attn_prefetch(base, (kt + 2) % 3, khb, vhb, (kt + 2) * 64, tid);
        }

        uint32_t kbase = base + (uint32_t)(kt % 3) * ATT_STG;
        uint32_t vbase = kbase + 9216 + lmrow;

        // S = Q K^T: trans-ldmatrix gives K^T[key][d] frags from [d][key] smem.
        float S[8][4];
#pragma unroll
        for (int j = 0; j < 8; j++) {
            S[j][0] = S[j][1] = S[j][2] = S[j][3] = 0.f;
            uint32_t addr = kbase + lmrowt + (uint32_t)(j * 16);
            uint32_t k0, k1, k2, k3, k4, k5, k6, k7;
            ldsm4t(k0, k1, k2, k3, addr);
            ldsm4t(k4, k5, k6, k7, addr + 32 * 144);
            {
                uint32_t bf[2] = { k0, k1 };
                mma_f16(S[j], Aq[0], bf);
            }
            {
                uint32_t bf[2] = { k2, k3 };
                mma_f16(S[j], Aq[1], bf);
            }
            {
                uint32_t bf[2] = { k4, k5 };
                mma_f16(S[j], Aq[2], bf);
            }
            {
                uint32_t bf[2] = { k6, k7 };
                mma_f16(S[j], Aq[3], bf);
            }
        }

        // Online softmax (log2 domain, f32 ex2 — R9 path)
        float tlo = -1e30f, thi = -1e30f;
#pragma unroll
        for (int j = 0; j < 8; j++) {
            tlo = fmaxf(tlo, fmaxf(S[j][0], S[j][1]));
            thi = fmaxf(thi, fmaxf(S[j][2], S[j][3]));
        }
#pragma unroll
        for (int o = 1; o <= 2; o <<= 1) {
            tlo = fmaxf(tlo, __shfl_xor_sync(0xffffffffu, tlo, o));
            thi = fmaxf(thi, __shfl_xor_sync(0xffffffffu, thi, o));
        }
        float nlo = fmaxf(mlo, tlo), nhi = fmaxf(mhi, thi);
        float clo = ex2f(mlo - nlo), chi = ex2f(mhi - nhi);
        mlo = nlo; mhi = nhi;
        float ssl = 0.f, ssh = 0.f;
        uint32_t Pf[8][2];
#pragma unroll
        for (int j = 0; j < 8; j++) {
            float p0 = ex2f(S[j][0] - nlo);
            float p1 = ex2f(S[j][1] - nlo);
            float p2 = ex2f(S[j][2] - nhi);
            float p3 = ex2f(S[j][3] - nhi);
            ssl += p0 + p1; ssh += p2 + p3;
            O[j][0] *= clo; O[j][1] *= clo; O[j][2] *= chi; O[j][3] *= chi;
            Pf[j][0] = f16x2(p0, p1);
            Pf[j][1] = f16x2(p2, p3);
        }
#pragma unroll
        for (int o = 1; o <= 2; o <<= 1) {
            ssl += __shfl_xor_sync(0xffffffffu, ssl, o);
            ssh += __shfl_xor_sync(0xffffffffu, ssh, o);
        }
        slo = slo * clo + ssl;
        shi = shi * chi + ssh;

        // O += P @ V  (register-relay P; non-trans ldmatrix V fragments)
#pragma unroll
        for (int j = 0; j < 8; j++) {
            uint32_t v0, v1, v2, v3, v4, v5, v6, v7;
            ldsm4(v0, v1, v2, v3, vbase + (uint32_t)(j * 1152));
            ldsm4(v4, v5, v6, v7, vbase + (uint32_t)(j * 1152 + 64));
            {
                uint32_t bf[2] = { v0, v1 };
                mma_f16(O[j], &Pf[0][0], bf);
            }
            {
                uint32_t bf[2] = { v2, v3 };
                mma_f16(O[j], &Pf[2][0], bf);
            }
            {
                uint32_t bf[2] = { v4, v5 };
                mma_f16(O[j], &Pf[4][0], bf);
            }
            {
                uint32_t bf[2] = { v6, v7 };
                mma_f16(O[j], &Pf[6][0], bf);
            }
        }
    }

    // Epilogue: normalize, write fp16 ao_t[b][q][c]
    uint16_t* aob = g_aot + ((size_t)b * N_) * C_ + h * HD_;
    float ilo = 1.f / slo, ihi = 1.f / shi;
#pragma unroll
    for (int j = 0; j < 8; j++) {
        int d = j * 8 + 2 * m;
        *(uint32_t*)&aob[(size_t)qlo * C_ + d] = f16x2(O[j][0] * ilo, O[j][1] * ilo);
        *(uint32_t*)&aob[(size_t)qhi * C_ + d] = f16x2(O[j][2] * ihi, O[j][3] * ihi);
    }
}

// ---------------------------------------------------------------------------
// Launch sequence (6 launches)
// ---------------------------------------------------------------------------
extern "C" void kernel_launch(void* const* d_in, const int* in_sizes, int n_in,
                              void* d_out, int out_size) {
    const float* x    = (const float*)d_in[0];
    const float* gw   = (const float*)d_in[1];
    const float* gb   = (const float*)d_in[2];
    const float* qkvw = (const float*)d_in[3];
    const float* qkvb = (const float*)d_in[4];
    const float* pw   = (const float*)d_in[5];
    const float* pb   = (const float*)d_in[6];
    float* out = (float*)d_out;

    uint16_t *hnt, *qkvh, *aot, *w16;
    cudaGetSymbolAddress((void**)&hnt,  g_hnt);
    cudaGetSymbolAddress((void**)&qkvh, g_qkvh);
    cudaGetSymbolAddress((void**)&aot,  g_aot);
    cudaGetSymbolAddress((void**)&w16,  g_w16);

    gn_stats1_k<<<256, 256>>>(x);
    w2h_k<<<(ALLW4 + 255) / 256, 256>>>(qkvw, pw);
    {
        dim3 g(N_ / 64, C_ / 64, B_);
        gn_t_k<<<g, 256>>>(x, gw, gb);
    }
    {
        dim3 g(N_ / 64, (3 * C_) / 64, B_);
        hgemm_k<<<g, 128>>>(w16, hnt, qkvb, nullptr, qkvh, nullptr, 3 * C_);
    }
    cudaFuncSetAttribute(attn_k, cudaFuncAttributeMaxDynamicSharedMemorySize, ATT_SMEM);
    {
        dim3 g(N_ / 64, NH_, B_);
        attn_k<<<g, 128, ATT_SMEM>>>();
    }
    {
        dim3 g(N_ / 64, C_ / 64, B_);
        hgemm_k<<<g, 128>>>(w16 + 3 * C_ * C_, aot, pb, x, nullptr, out, C_);
    }
}

// round 17
// speedup vs baseline: 1.0233x; 1.0233x over previous
#include <cuda_runtime.h>
#include <cuda_fp16.h>
#include <cstdint>

// Problem constants
#define B_   4
#define C_   256
#define N_   4096          // H*W = 64*64
#define NH_  4
#define HD_  64
#define NG_  8
#define CPG_ 32
#define EPS_ 1e-5f
#define SCALE_ 0.125f      // HD^-0.5
#define LOG2E_ 1.4426950408889634f

// Scratch
__device__ uint16_t g_hnt [(size_t)B_ * N_ * C_];       // GN output, fp16 [b][n][c]
__device__ uint16_t g_qkvh[(size_t)B_ * 3 * C_ * N_];   // QKV fp16 [b][3C][n]
__device__ uint16_t g_aot [(size_t)B_ * N_ * C_];       // attn out fp16 [b][n][c]
__device__ uint16_t g_w16 [(3 * C_ + C_) * C_];         // qkv_w + proj_w fp16
__device__ float    g_part[256 * 2];                    // partial GN sums

// ---------------------------------------------------------------------------
// helpers
// ---------------------------------------------------------------------------
__device__ __forceinline__ float ex2f(float x) {
    float y;
    asm("ex2.approx.ftz.f32 %0, %1;" : "=f"(y) : "f"(x));
    return y;
}
__device__ __forceinline__ uint32_t f16x2(float a, float b) {   // {lo:a, hi:b}
    uint32_t r;
    asm("cvt.rn.f16x2.f32 %0, %1, %2;" : "=r"(r) : "f"(b), "f"(a));
    return r;
}
__device__ __forceinline__ uint32_t smem_u32(const void* p) {
    uint32_t a;
    asm("{ .reg .u64 t; cvta.to.shared.u64 t, %1; cvt.u32.u64 %0, t; }" : "=r"(a) : "l"(p));
    return a;
}
__device__ __forceinline__ void cpa16(uint32_t s, const void* g) {
    asm volatile("cp.async.cg.shared.global [%0], [%1], 16;" :: "r"(s), "l"(g));
}
__device__ __forceinline__ void cpa_commit() { asm volatile("cp.async.commit_group;"); }
__device__ __forceinline__ void cpa_wait1()  { asm volatile("cp.async.wait_group 1;"); }
__device__ __forceinline__ void cpa_wait0()  { asm volatile("cp.async.wait_group 0;"); }

__device__ __forceinline__ void ldsm4(uint32_t& r0, uint32_t& r1, uint32_t& r2, uint32_t& r3,
                                      uint32_t a) {
    asm volatile("ldmatrix.sync.aligned.m8n8.x4.shared.b16 {%0,%1,%2,%3}, [%4];"
                 : "=r"(r0), "=r"(r1), "=r"(r2), "=r"(r3) : "r"(a));
}
__device__ __forceinline__ void ldsm4t(uint32_t& r0, uint32_t& r1, uint32_t& r2, uint32_t& r3,
                                       uint32_t a) {
    asm volatile("ldmatrix.sync.aligned.m8n8.x4.trans.shared.b16 {%0,%1,%2,%3}, [%4];"
                 : "=r"(r0), "=r"(r1), "=r"(r2), "=r"(r3) : "r"(a));
}
__device__ __forceinline__ void mma_f16(float* d, const uint32_t* a, const uint32_t* b) {
    asm("mma.sync.aligned.m16n8k16.row.col.f32.f16.f16.f32 "
        "{%0,%1,%2,%3}, {%4,%5,%6,%7}, {%8,%9}, {%0,%1,%2,%3};"
        : "+f"(d[0]), "+f"(d[1]), "+f"(d[2]), "+f"(d[3])
        : "r"(a[0]), "r"(a[1]), "r"(a[2]), "r"(a[3]), "r"(b[0]), "r"(b[1]));
}

// ---------------------------------------------------------------------------
// GroupNorm statistics, phase 1: 256 blocks, 8 partials per (b,g)
// ---------------------------------------------------------------------------
__global__ void gn_stats1_k(const float* __restrict__ x) {
    int blk = blockIdx.x;
    int bg = blk >> 3, part = blk & 7;
    const float4* base = (const float4*)(x + (size_t)bg * CPG_ * N_) + part * 4096;
    int tid = threadIdx.x;
    float s = 0.f, s2 = 0.f;
    for (int i = tid; i < 4096; i += 256) {
        float4 v = base[i];
        s  += v.x + v.y + v.z + v.w;
        s2 += v.x * v.x + v.y * v.y + v.z * v.z + v.w * v.w;
    }
    __shared__ float rs[256], rq[256];
    rs[tid] = s; rq[tid] = s2;
    __syncthreads();
    for (int o = 128; o > 0; o >>= 1) {
        if (tid < o) { rs[tid] += rs[tid + o]; rq[tid] += rq[tid + o]; }
        __syncthreads();
    }
    if (tid == 0) {
        g_part[blk * 2 + 0] = rs[0];
        g_part[blk * 2 + 1] = rq[0];
    }
}

// ---------------------------------------------------------------------------
// GroupNorm apply + transpose, with inline phase-2 stats reduction.
// ---------------------------------------------------------------------------
__global__ void gn_t_k(const float* __restrict__ x,
                       const float* __restrict__ gw,
                       const float* __restrict__ gb) {
    int n0 = blockIdx.x * 64, c0 = blockIdx.y * 64, b = blockIdx.z;
    int t = threadIdx.x;

    __shared__ __half ht[64][72];
    __shared__ float sstat[2][2];

    if (t < 2) {
        int g_abs = b * NG_ + (c0 >> 5) + t;
        float s = 0.f, s2 = 0.f;
#pragma unroll
        for (int p = 0; p < 8; p++) {
            s  += g_part[(g_abs * 8 + p) * 2 + 0];
            s2 += g_part[(g_abs * 8 + p) * 2 + 1];
        }
        const float invn = 1.f / (float)(CPG_ * N_);
        float mean = s * invn;
        float var  = s2 * invn - mean * mean;
        sstat[t][0] = mean;
        sstat[t][1] = rsqrtf(var + EPS_);
    }
    __syncthreads();

    int n_l = t & 63, cq = t >> 6;
#pragma unroll
    for (int it = 0; it < 16; it++) {
        int c_l = it * 4 + cq;
        int c = c0 + c_l;
        int gi = c_l >> 5;
        float mean = sstat[gi][0];
        float rstd = sstat[gi][1];
        float ga = gw[c] * rstd;
        float be = gb[c] - mean * ga;
        float v = x[((size_t)b * C_ + c) * N_ + n0 + n_l];
        ht[c_l][n_l] = __float2half(v * ga + be);
    }
    __syncthreads();

    int n_o = t >> 2, ch = t & 3;
    uint32_t pk[8];
#pragma unroll
    for (int u = 0; u < 8; u++) {
        __half2 h2 = __halves2half2(ht[ch * 16 + 2 * u][n_o], ht[ch * 16 + 2 * u + 1][n_o]);
        pk[u] = *(uint32_t*)&h2;
    }
    uint16_t* orow = g_hnt + ((size_t)b * N_ + n0 + n_o) * C_ + c0 + ch * 16;
    *(uint4*)(orow)     = *(uint4*)&pk[0];
    *(uint4*)(orow + 8) = *(uint4*)&pk[4];
}

// ---------------------------------------------------------------------------
// Weight pack fp32 -> fp16 (both weights in one launch)
// ---------------------------------------------------------------------------
#define QKVW4 (3 * C_ * C_ / 4)   // 49152 float4
#define ALLW4 (QKVW4 + C_ * C_ / 4)
__global__ void w2h_k(const float* __restrict__ qkvw, const float* __restrict__ pw) {
    int i = blockIdx.x * 256 + threadIdx.x;
    if (i >= ALLW4) return;
    float4 v = (i < QKVW4) ? ((const float4*)qkvw)[i] : ((const float4*)pw)[i - QKVW4];
    uint2 o;
    o.x = f16x2(v.x, v.y);
    o.y = f16x2(v.z, v.w);
    *(uint2*)(g_w16 + (size_t)i * 4) = o;
}

// ---------------------------------------------------------------------------
// fp16 tensor-core GEMM: CTA 128m x 64n, 4 warps, warp = 32m x 64n
// (two m16 blocks per warp -> B-frag ldsm4 amortized over 2x MMAs).
// Single-sync pipeline: wait -> sync -> prefetch(next) -> compute.
// ---------------------------------------------------------------------------
__global__ __launch_bounds__(128) void hgemm_k(const uint16_t* __restrict__ W16,
                                               const uint16_t* __restrict__ Bt,
                                               const float* __restrict__ bias,
                                               const float* __restrict__ res,
                                               uint16_t* __restrict__ outh,
                                               float* __restrict__ outf,
                                               int M) {
    const int K = C_;
    int b  = blockIdx.z;
    const uint16_t* Btb = Bt + (size_t)b * N_ * K;
    int m0 = blockIdx.y * 128, n0 = blockIdx.x * 64;

    __shared__ uint16_t Bs[2][64 * 72];
    uint32_t bsm[2] = { smem_u32(Bs[0]), smem_u32(Bs[1]) };

    int tid = threadIdx.x, w = tid >> 5, lane = tid & 31;
    int g = lane >> 2, m = lane & 3;
    // warp covers m-rows [m0 + w*32, m0 + w*32 + 32): two m16 blocks
    int r0 = m0 + w * 32 + g;      // block0 lo row; block1 = +16
    uint32_t lmrow = (uint32_t)((lane & 7) * 144 + (lane >> 3) * 16);

    float acc[2][8][4];
#pragma unroll
    for (int mb = 0; mb < 2; mb++)
#pragma unroll
        for (int j = 0; j < 8; j++)
#pragma unroll
            for (int i = 0; i < 4; i++) acc[mb][j][i] = 0.f;

    const int NS = K / 32;
    {
#pragma unroll
        for (int it = 0; it < 2; it++) {
            int idx = it * 128 + tid;
            int r = idx >> 2, c = idx & 3;
            cpa16(bsm[0] + (uint32_t)(r * 144 + c * 16),
                  Btb + (size_t)(n0 + r) * K + c * 8);
        }
        cpa_commit();
    }
    for (int ks = 0; ks < NS; ks++) {
        cpa_wait0();
        __syncthreads();
        if (ks + 1 < NS) {
            int s = (ks + 1) & 1, k0 = (ks + 1) * 32;
#pragma unroll
            for (int it = 0; it < 2; it++) {
                int idx = it * 128 + tid;
                int r = idx >> 2, c = idx & 3;
                cpa16(bsm[s] + (uint32_t)(r * 144 + c * 16),
                      Btb + (size_t)(n0 + r) * K + k0 + c * 8);
            }
            cpa_commit();
        }
        int k0 = ks * 32;
        // A-frags: [m-block][k-chunk][4]
        uint32_t a[2][2][4];
#pragma unroll
        for (int mb = 0; mb < 2; mb++) {
            int rl = r0 + mb * 16, rh = rl + 8;
            int kk = k0 + 2 * m;
            a[mb][0][0] = *(const uint32_t*)&W16[(size_t)rl * K + kk];
            a[mb][0][1] = *(const uint32_t*)&W16[(size_t)rh * K + kk];
            a[mb][0][2] = *(const uint32_t*)&W16[(size_t)rl * K + kk + 8];
            a[mb][0][3] = *(const uint32_t*)&W16[(size_t)rh * K + kk + 8];
            a[mb][1][0] = *(const uint32_t*)&W16[(size_t)rl * K + kk + 16];
            a[mb][1][1] = *(const uint32_t*)&W16[(size_t)rh * K + kk + 16];
            a[mb][1][2] = *(const uint32_t*)&W16[(size_t)rl * K + kk + 24];
            a[mb][1][3] = *(const uint32_t*)&W16[(size_t)rh * K + kk + 24];
        }
        uint32_t bbase = bsm[ks & 1] + lmrow;
#pragma unroll
        for (int j = 0; j < 8; j++) {
            uint32_t b0, b1, b2, b3;
            ldsm4(b0, b1, b2, b3, bbase + (uint32_t)(j * 1152));
            uint32_t bf0[2] = { b0, b1 };
            uint32_t bf1[2] = { b2, b3 };
#pragma unroll
            for (int mb = 0; mb < 2; mb++) {
                mma_f16(acc[mb][j], a[mb][0], bf0);
                mma_f16(acc[mb][j], a[mb][1], bf1);
            }
        }
    }

#pragma unroll
    for (int mb = 0; mb < 2; mb++) {
        int rl = r0 + mb * 16, rh = rl + 8;
        float b_lo = bias[rl], b_hi = bias[rh];
        if (outh) {
            uint16_t* Ob = outh + (size_t)b * M * N_;
#pragma unroll
            for (int j = 0; j < 8; j++) {
                int n = n0 + j * 8 + 2 * m;
                *(uint32_t*)&Ob[(size_t)rl * N_ + n] = f16x2(acc[mb][j][0] + b_lo, acc[mb][j][1] + b_lo);
                *(uint32_t*)&Ob[(size_t)rh * N_ + n] = f16x2(acc[mb][j][2] + b_hi, acc[mb][j][3] + b_hi);
            }
        } else {
            float* Ob = outf + (size_t)b * M * N_;
            const float* resb = res + (size_t)b * M * N_;
#pragma unroll
            for (int j = 0; j < 8; j++) {
                int n = n0 + j * 8 + 2 * m;
                size_t olo = (size_t)rl * N_ + n;
                size_t ohi = (size_t)rh * N_ + n;
                float2 rlv = *(const float2*)&resb[olo];
                float2 rhv = *(const float2*)&resb[ohi];
                float2 vlo; vlo.x = acc[mb][j][0] + b_lo + rlv.x; vlo.y = acc[mb][j][1] + b_lo + rlv.y;
                float2 vhi; vhi.x = acc[mb][j][2] + b_hi + rhv.x; vhi.y = acc[mb][j][3] + b_hi + rhv.y;
                *(float2*)&Ob[olo] = vlo;
                *(float2*)&Ob[ohi] = vhi;
            }
        }
    }
}

// ---------------------------------------------------------------------------
// Flash attention (unchanged from R15 WIN): 64q/CTA, 4 warps, trans-ldmatrix K,
// single-sync 3-stage cp.async, f32 softmax.
// ---------------------------------------------------------------------------
#define ATT_STG   18432          // bytes per stage (K 9216 + V 9216)
#define ATT_SMEM  (3 * ATT_STG)  // 55296

__device__ __forceinline__ void attn_prefetch(uint32_t base, int stg,
                                              const uint16_t* khb, const uint16_t* vhb,
                                              int k0t, int tid) {
    uint32_t kb = base + (uint32_t)stg * ATT_STG;
    uint32_t vb = kb + 9216;
#pragma unroll
    for (int it = 0; it < 4; it++) {
        int idx = it * 128 + tid;
        int r = idx >> 3, c = idx & 7;
        cpa16(kb + (uint32_t)(r * 144 + c * 16), khb + (size_t)r * N_ + k0t + c * 8);
    }
#pragma unroll
    for (int it = 0; it < 4; it++) {
        int idx = it * 128 + tid;
        int r = idx >> 3, c = idx & 7;
        cpa16(vb + (uint32_t)(r * 144 + c * 16), vhb + (size_t)r * N_ + k0t + c * 8);
    }
    cpa_commit();
}

__global__ __launch_bounds__(128, 4) void attn_k() {
    int qt = blockIdx.x, h = blockIdx.y, b = blockIdx.z;
    const uint16_t* qb  = g_qkvh + ((size_t)b * 3 * C_ + h * HD_) * N_;
    const uint16_t* khb = g_qkvh + ((size_t)b * 3 * C_ + C_ + h * HD_) * N_;
    const uint16_t* vhb = g_qkvh + ((size_t)b * 3 * C_ + 2 * C_ + h * HD_) * N_;

    extern __shared__ uint16_t smh[];
    uint32_t base = smem_u32(smh);

    int tid = threadIdx.x, w = tid >> 5, lane = tid & 31;
    int g = lane >> 2, m = lane & 3;
    int q0 = qt * 64;
    uint32_t lmrow  = (uint32_t)((lane & 7) * 144 + (lane >> 3) * 16);  // V (non-trans)
    uint32_t lmrowt = (uint32_t)(lane * 144);                           // K (trans)

    attn_prefetch(base, 0, khb, vhb, 0, tid);
    attn_prefetch(base, 1, khb, vhb, 64, tid);

    // Q A-fragments (fp16), scaled for log2-domain softmax
    const float qs = SCALE_ * LOG2E_;
    uint32_t Aq[4][4];
    int qlo = q0 + w * 16 + g, qhi = qlo + 8;
#pragma unroll
    for (int t = 0; t < 4; t++) {
        int d0 = t * 16 + 2 * m;
#pragma unroll
        for (int hseg = 0; hseg < 2; hseg++) {
            int d = d0 + hseg * 8;
            float a0 = __half2float(__ushort_as_half(qb[(size_t)d * N_ + qlo])) * qs;
            float a1 = __half2float(__ushort_as_half(qb[(size_t)(d + 1) * N_ + qlo])) * qs;
            float a2 = __half2float(__ushort_as_half(qb[(size_t)d * N_ + qhi])) * qs;
            float a3 = __half2float(__ushort_as_half(qb[(size_t)(d + 1) * N_ + qhi])) * qs;
            Aq[t][2 * hseg]     = f16x2(a0, a1);
            Aq[t][2 * hseg + 1] = f16x2(a2, a3);
        }
    }

    float O[8][4];
#pragma unroll
    for (int j = 0; j < 8; j++)
#pragma unroll
        for (int i = 0; i < 4; i++) O[j][i] = 0.f;
    float mlo = -1e30f, mhi = -1e30f, slo = 0.f, shi = 0.f;

    const int NT = N_ / 64;
    for (int kt = 0; kt < NT; kt++) {
        if (kt + 1 < NT) {
            cpa_wait1();
        } else {
            cpa_wait0();
        }
        __syncthreads();
        if (kt + 2 < NT) {
            attn_prefetch(base, (kt + 2) % 3, khb, vhb, (kt + 2) * 64, tid);
        }

        uint32_t kbase = base + (uint32_t)(kt % 3) * ATT_STG;
        uint32_t vbase = kbase + 9216 + lmrow;

        // S = Q K^T (trans-ldmatrix K frags)
        float S[8][4];
#pragma unroll
        for (int j = 0; j < 8; j++) {
            S[j][0] = S[j][1] = S[j][2] = S[j][3] = 0.f;
            uint32_t addr = kbase + lmrowt + (uint32_t)(j * 16);
            uint32_t k0, k1, k2, k3, k4, k5, k6, k7;
            ldsm4t(k0, k1, k2, k3, addr);
            ldsm4t(k4, k5, k6, k7, addr + 32 * 144);
            {
                uint32_t bf[2] = { k0, k1 };
                mma_f16(S[j], Aq[0], bf);
            }
            {
                uint32_t bf[2] = { k2, k3 };
                mma_f16(S[j], Aq[1], bf);
            }
            {
                uint32_t bf[2] = { k4, k5 };
                mma_f16(S[j], Aq[2], bf);
            }
            {
                uint32_t bf[2] = { k6, k7 };
                mma_f16(S[j], Aq[3], bf);
            }
        }

        // Online softmax (log2 domain, f32 ex2)
        float tlo = -1e30f, thi = -1e30f;
#pragma unroll
        for (int j = 0; j < 8; j++) {
            tlo = fmaxf(tlo, fmaxf(S[j][0], S[j][1]));
            thi = fmaxf(thi, fmaxf(S[j][2], S[j][3]));
        }
#pragma unroll
        for (int o = 1; o <= 2; o <<= 1) {
            tlo = fmaxf(tlo, __shfl_xor_sync(0xffffffffu, tlo, o));
            thi = fmaxf(thi, __shfl_xor_sync(0xffffffffu, thi, o));
        }
        float nlo = fmaxf(mlo, tlo), nhi = fmaxf(mhi, thi);
        float clo = ex2f(mlo - nlo), chi = ex2f(mhi - nhi);
        mlo = nlo; mhi = nhi;
        float ssl = 0.f, ssh = 0.f;
        uint32_t Pf[8][2];
#pragma unroll
        for (int j = 0; j < 8; j++) {
            float p0 = ex2f(S[j][0] - nlo);
            float p1 = ex2f(S[j][1] - nlo);
            float p2 = ex2f(S[j][2] - nhi);
            float p3 = ex2f(S[j][3] - nhi);
            ssl += p0 + p1; ssh += p2 + p3;
            O[j][0] *= clo; O[j][1] *= clo; O[j][2] *= chi; O[j][3] *= chi;
            Pf[j][0] = f16x2(p0, p1);
            Pf[j][1] = f16x2(p2, p3);
        }
#pragma unroll
        for (int o = 1; o <= 2; o <<= 1) {
            ssl += __shfl_xor_sync(0xffffffffu, ssl, o);
            ssh += __shfl_xor_sync(0xffffffffu, ssh, o);
        }
        slo = slo * clo + ssl;
        shi = shi * chi + ssh;

        // O += P @ V
#pragma unroll
        for (int j = 0; j < 8; j++) {
            uint32_t v0, v1, v2, v3, v4, v5, v6, v7;
            ldsm4(v0, v1, v2, v3, vbase + (uint32_t)(j * 1152));
            ldsm4(v4, v5, v6, v7, vbase + (uint32_t)(j * 1152 + 64));
            {
                uint32_t bf[2] = { v0, v1 };
                mma_f16(O[j], &Pf[0][0], bf);
            }
            {
                uint32_t bf[2] = { v2, v3 };
                mma_f16(O[j], &Pf[2][0], bf);
            }
            {
                uint32_t bf[2] = { v4, v5 };
                mma_f16(O[j], &Pf[4][0], bf);
            }
            {
                uint32_t bf[2] = { v6, v7 };
                mma_f16(O[j], &Pf[6][0], bf);
            }
        }
    }

    // Epilogue
    uint16_t* aob = g_aot + ((size_t)b * N_) * C_ + h * HD_;
    float ilo = 1.f / slo, ihi = 1.f / shi;
#pragma unroll
    for (int j = 0; j < 8; j++) {
        int d = j * 8 + 2 * m;
        *(uint32_t*)&aob[(size_t)qlo * C_ + d] = f16x2(O[j][0] * ilo, O[j][1] * ilo);
        *(uint32_t*)&aob[(size_t)qhi * C_ + d] = f16x2(O[j][2] * ihi, O[j][3] * ihi);
    }
}

// ---------------------------------------------------------------------------
// Launch sequence (6 launches)
// ---------------------------------------------------------------------------
extern "C" void kernel_launch(void* const* d_in, const int* in_sizes, int n_in,
                              void* d_out, int out_size) {
    const float* x    = (const float*)d_in[0];
    const float* gw   = (const float*)d_in[1];
    const float* gb   = (const float*)d_in[2];
    const float* qkvw = (const float*)d_in[3];
    const float* qkvb = (const float*)d_in[4];
    const float* pw   = (const float*)d_in[5];
    const float* pb   = (const float*)d_in[6];
    float* out = (float*)d_out;

    uint16_t *hnt, *qkvh, *aot, *w16;
    cudaGetSymbolAddress((void**)&hnt,  g_hnt);
    cudaGetSymbolAddress((void**)&qkvh, g_qkvh);
    cudaGetSymbolAddress((void**)&aot,  g_aot);
    cudaGetSymbolAddress((void**)&w16,  g_w16);

    gn_stats1_k<<<256, 256>>>(x);
    w2h_k<<<(ALLW4 + 255) / 256, 256>>>(qkvw, pw);
    {
        dim3 g(N_ / 64, C_ / 64, B_);
        gn_t_k<<<g, 256>>>(x, gw, gb);
    }
    {
        dim3 g(N_ / 64, (3 * C_) / 128, B_);
        hgemm_k<<<g, 128>>>(w16, hnt, qkvb, nullptr, qkvh, nullptr, 3 * C_);
    }
    cudaFuncSetAttribute(attn_k, cudaFuncAttributeMaxDynamicSharedMemorySize, ATT_SMEM);
    {
        dim3 g(N_ / 64, NH_, B_);
        attn_k<<<g, 128, ATT_SMEM>>>();
    }
    {
        dim3 g(N_ / 64, C_ / 128, B_);
        hgemm_k<<<g, 128>>>(w16 + 3 * C_ * C_, aot, pb, x, nullptr, out, C_);
    }
}